// round 11
// baseline (speedup 1.0000x reference)
#include <cuda_runtime.h>
#include <cuda_bf16.h>
#include <math.h>
#include <stdint.h>

// Problem constants (fixed by setup_inputs)
#define T_STEPS 512
#define BATCH   64
#define HID     512
#define GDIM    2048   // 4*H
#define DDIM    512
#define MROWS   (T_STEPS * BATCH)   // 32768

typedef unsigned long long ull;

// ---- scratch (device globals: allocation-free rule) ----
__device__ float g_xproj[(size_t)MROWS * GDIM];                 // 268 MB
__device__ __align__(16) __nv_bfloat16 g_xhi[(size_t)MROWS * DDIM];
__device__ __align__(16) __nv_bfloat16 g_xlo[(size_t)MROWS * DDIM];
__device__ __align__(16) __nv_bfloat16 g_wthi[(size_t)GDIM * DDIM];
__device__ __align__(16) __nv_bfloat16 g_wtlo[(size_t)GDIM * DDIM];
__device__ __align__(16) __nv_bfloat16 g_hhi[2][BATCH * HID];   // double buffer, pre-masked
__device__ __align__(16) __nv_bfloat16 g_hlo[2][BATCH * HID];
__device__ __align__(128) unsigned int g_bcount[4 * 32];        // per-group counters (128B apart)
__device__ __align__(128) unsigned int g_bgen[4 * 32];

__device__ __forceinline__ float sigmoidf_(float x) { return 1.0f / (1.0f + expf(-x)); }

__device__ __forceinline__ uint32_t smem_u32(const void* p) {
    uint32_t a;
    asm("{ .reg .u64 t; cvta.to.shared.u64 t, %1; cvt.u32.u64 %0, t; }" : "=r"(a) : "l"(p));
    return a;
}

#define CP_ASYNC16(dst, src) \
    asm volatile("cp.async.cg.shared.global [%0], [%1], 16;" :: "r"(dst), "l"(src))
#define CP_COMMIT()   asm volatile("cp.async.commit_group;" ::: "memory")
#define CP_WAIT(n)    asm volatile("cp.async.wait_group %0;" :: "n"(n) : "memory")

#define LDSM_X4(r0, r1, r2, r3, a) \
    asm volatile("ldmatrix.sync.aligned.m8n8.x4.shared.b16 {%0,%1,%2,%3}, [%4];" \
                 : "=r"(r0), "=r"(r1), "=r"(r2), "=r"(r3) : "r"(a))
#define LDSM_X2(r0, r1, a) \
    asm volatile("ldmatrix.sync.aligned.m8n8.x2.shared.b16 {%0,%1}, [%2];" \
                 : "=r"(r0), "=r"(r1) : "r"(a))
#define MMA16816(d, a, b0, b1) \
    asm volatile("mma.sync.aligned.m16n8k16.row.col.f32.bf16.bf16.f32 " \
                 "{%0,%1,%2,%3}, {%4,%5,%6,%7}, {%8,%9}, {%0,%1,%2,%3};" \
                 : "+f"((d)[0]), "+f"((d)[1]), "+f"((d)[2]), "+f"((d)[3]) \
                 : "r"((a)[0]), "r"((a)[1]), "r"((a)[2]), "r"((a)[3]), "r"(b0), "r"(b1))

// =====================================================================
// k_convert_x / k_convert_w (unchanged)
// =====================================================================
__global__ __launch_bounds__(256) void k_convert_x(const float* __restrict__ x) {
    size_t i = (size_t)blockIdx.x * 256 + threadIdx.x;
    float4 v = ((const float4*)x)[i];
    __nv_bfloat162 h01 = __float22bfloat162_rn(make_float2(v.x, v.y));
    __nv_bfloat162 h23 = __float22bfloat162_rn(make_float2(v.z, v.w));
    float2 f01 = __bfloat1622float2(h01);
    float2 f23 = __bfloat1622float2(h23);
    __nv_bfloat162 l01 = __float22bfloat162_rn(make_float2(v.x - f01.x, v.y - f01.y));
    __nv_bfloat162 l23 = __float22bfloat162_rn(make_float2(v.z - f23.x, v.w - f23.y));
    uint2 hv, lv;
    hv.x = *(uint32_t*)&h01; hv.y = *(uint32_t*)&h23;
    lv.x = *(uint32_t*)&l01; lv.y = *(uint32_t*)&l23;
    ((uint2*)g_xhi)[i] = hv;
    ((uint2*)g_xlo)[i] = lv;
}

__global__ __launch_bounds__(256) void k_convert_w(const float* __restrict__ Wx) {
    __shared__ float tile[32][33];
    const int n0 = blockIdx.x * 32;
    const int k0 = blockIdx.y * 32;
    const int c = threadIdx.x & 31, r = threadIdx.x >> 5;
#pragma unroll
    for (int i = 0; i < 4; i++)
        tile[r + i * 8][c] = Wx[(size_t)(k0 + r + i * 8) * GDIM + n0 + c];
    __syncthreads();
#pragma unroll
    for (int i = 0; i < 4; i++) {
        int nn = r + i * 8;
        float v = tile[c][nn];
        __nv_bfloat16 hi = __float2bfloat16_rn(v);
        g_wthi[(size_t)(n0 + nn) * DDIM + k0 + c] = hi;
        g_wtlo[(size_t)(n0 + nn) * DDIM + k0 + c] =
            __float2bfloat16_rn(v - __bfloat162float(hi));
    }
}

// =====================================================================
// k_xproj_hmma (unchanged from round 7)
// =====================================================================
#define XSTAGE 32768
#define XSMEM  (2 * XSTAGE)

__global__ __launch_bounds__(256, 2) void k_xproj_hmma(const float* __restrict__ bias) {
    extern __shared__ char xsm[];
    const uint32_t smb = smem_u32(xsm);
    const int tid = threadIdx.x, lane = tid & 31, wid = tid >> 5;
    const int n0 = blockIdx.x * 128;
    const int m0 = blockIdx.y * 128;
    const int wm = wid & 3, wn = wid >> 2;

    const int sr = tid >> 1;
    const int spl = tid & 1;
    const uint32_t sdst0 = (uint32_t)(sr * 128);
    const int sswz = sr & 7;

    float acc[2][8][4];
#pragma unroll
    for (int mi = 0; mi < 2; mi++)
#pragma unroll
        for (int g = 0; g < 8; g++)
#pragma unroll
            for (int q = 0; q < 4; q++) acc[mi][g][q] = 0.0f;

    const __nv_bfloat16* asrc = (spl ? g_xlo : g_xhi) + (size_t)(m0 + sr) * DDIM;
    const __nv_bfloat16* bsrc = (spl ? g_wtlo : g_wthi) + (size_t)(n0 + sr) * DDIM;

#pragma unroll
    for (int jj = 0; jj < 4; jj++) {
        int j = spl * 4 + jj;
        uint32_t dA = smb + sdst0 + (uint32_t)((j ^ sswz) << 4);
        CP_ASYNC16(dA, asrc + jj * 8);
        CP_ASYNC16(dA + 16384, bsrc + jj * 8);
    }
    CP_COMMIT();

    for (int s = 0; s < 16; s++) {
        if (s < 15) {
            int k0 = (s + 1) * 32;
            uint32_t bufn = ((uint32_t)(s + 1) & 1) * XSTAGE;
#pragma unroll
            for (int jj = 0; jj < 4; jj++) {
                int j = spl * 4 + jj;
                uint32_t dA = smb + bufn + sdst0 + (uint32_t)((j ^ sswz) << 4);
                CP_ASYNC16(dA, asrc + k0 + jj * 8);
                CP_ASYNC16(dA + 16384, bsrc + k0 + jj * 8);
            }
            CP_COMMIT();
            CP_WAIT(1);
        } else {
            CP_WAIT(0);
        }
        __syncthreads();

        const uint32_t Ab = smb + ((uint32_t)s & 1) * XSTAGE;
        const uint32_t Bb = Ab + 16384;
#pragma unroll
        for (int kk = 0; kk < 2; kk++) {
            uint32_t ah[2][4], al[2][4];
#pragma unroll
            for (int mi = 0; mi < 2; mi++) {
                int ar = wm * 32 + mi * 16 + (lane & 15);
                int uh = kk * 2 + ((lane >> 4) & 1);
                uint32_t base = Ab + (uint32_t)(ar * 128);
                int s7 = ar & 7;
                LDSM_X4(ah[mi][0], ah[mi][1], ah[mi][2], ah[mi][3],
                        base + (uint32_t)((uh ^ s7) << 4));
                LDSM_X4(al[mi][0], al[mi][1], al[mi][2], al[mi][3],
                        base + (uint32_t)(((uh + 4) ^ s7) << 4));
            }
#pragma unroll
            for (int g = 0; g < 8; g++) {
                int br = wn * 64 + g * 8 + (lane & 7);
                int ub = kk * 2 + ((lane >> 3) & 1);
                uint32_t base = Bb + (uint32_t)(br * 128);
                int s7 = br & 7;
                uint32_t b0, b1, c0, c1;
                LDSM_X2(b0, b1, base + (uint32_t)((ub ^ s7) << 4));
                LDSM_X2(c0, c1, base + (uint32_t)(((ub + 4) ^ s7) << 4));
#pragma unroll
                for (int mi = 0; mi < 2; mi++) {
                    MMA16816(acc[mi][g], ah[mi], b0, b1);
                    MMA16816(acc[mi][g], al[mi], b0, b1);
                    MMA16816(acc[mi][g], ah[mi], c0, c1);
                }
            }
        }
        __syncthreads();
    }

#pragma unroll
    for (int mi = 0; mi < 2; mi++) {
        int gr = m0 + wm * 32 + mi * 16 + (lane >> 2);
#pragma unroll
        for (int g = 0; g < 8; g++) {
            int gc = n0 + wn * 64 + g * 8 + (lane & 3) * 2;
            float2 bb = *(const float2*)(bias + gc);
            float2 v0 = {acc[mi][g][0] + bb.x, acc[mi][g][1] + bb.y};
            float2 v1 = {acc[mi][g][2] + bb.x, acc[mi][g][3] + bb.y};
            *(float2*)(g_xproj + (size_t)gr * GDIM + gc)       = v0;
            *(float2*)(g_xproj + (size_t)(gr + 8) * GDIM + gc) = v1;
        }
    }
}

// =====================================================================
// k_rnn: persistent masked-LSTM recurrence on HMMA.
// Round 11: 4 INDEPENDENT groups of 32 CTAs (batch rows are independent
// recurrences). Group g owns batch rows [g*16,(g+1)*16); CTA loc in a
// group owns h-cols [loc*16, loc*16+16) = 64 gate cols. Barrier is
// per-group (32 arrivals, own cache line). Staging = 32KB/CTA/step.
// =====================================================================
#define NCTA  128
#define NTHR  512
#define GCTA  32     // CTAs per group
#define BROWS 16     // batch rows per group

#define OFF_A  0        // 16 rows x 2048B = 32768
#define OFF_B  32768    // 64 rows x 2048B = 131072
#define OFF_G  163840   // 2 x 16 x 65 floats = 8320
#define SMEM2  172160

__device__ __forceinline__ uint32_t swz(int row, int kbyte) {
    return (uint32_t)(row * 2048) + ((((uint32_t)kbyte >> 4) ^ (uint32_t)(row & 7)) << 4)
         + ((uint32_t)kbyte & 15u);
}

__global__ __launch_bounds__(NTHR, 1) void k_rnn(const float* __restrict__ h0,
                                                 const float* __restrict__ c0,
                                                 const float* __restrict__ mask,
                                                 const float* __restrict__ Wh,
                                                 float* __restrict__ out) {
    extern __shared__ char smraw[];
    const uint32_t smb = smem_u32(smraw);
    float* gates_s = (float*)(smraw + OFF_G);    // [2][16][65]
    const int tid = threadIdx.x, lane = tid & 31, wid = tid >> 5;
    const int cta = blockIdx.x;
    const int grp = cta >> 5;          // 0..3: batch group
    const int loc = cta & 31;          // h-col slice within group
    const int hc0 = loc * 16;          // first h-col owned
    const int brow0 = grp * BROWS;     // first batch row of group

    // ---- Wh slice -> B smem: 64 gate cols, split-bf16 (hi k<512, lo >=) ----
#pragma unroll 8
    for (int it = 0; it < 128; it++) {
        int e = tid + it * NTHR;           // 0..65535
        int n = e >> 10, k = e & 1023;     // n: 64 local gate cols
        int gcol = (n >> 4) * HID + hc0 + (n & 15);
        float v = Wh[(size_t)(k & 511) * GDIM + gcol];
        __nv_bfloat16 hi = __float2bfloat16_rn(v);
        __nv_bfloat16 bv = (k < 512) ? hi : __float2bfloat16_rn(v - __bfloat162float(hi));
        *(__nv_bfloat16*)(smraw + OFF_B + swz(n, k * 2)) = bv;
    }

    // MMA warp coords: 16 warps = 8 n-tiles x 2 k-halves
    const int nt = wid & 7, khalf = wid >> 3;
    const int ar = lane & 15;
    const uint32_t aRowBase = smb + OFF_A + (uint32_t)ar * 2048;
    const uint32_t sA = (uint32_t)(ar & 7) << 4;
    const uint32_t aHi = (uint32_t)((lane >> 4) & 1) << 4;
    const int br = nt * 8 + (lane & 7);
    const uint32_t bRowBase = smb + OFF_B + (uint32_t)br * 2048;
    const uint32_t sB = (uint32_t)(br & 7) << 4;
    const uint32_t bHi = (uint32_t)((lane >> 3) & 1) << 4;
    const int kcb = khalf * 16;

    // staging coords: row = tid>>5 (16 rows), unit j = tid&31, 4 units/thread
    const int strow = tid >> 5;
    const int stj   = tid & 31;

    // update mapping: 256 threads, 1 element each: (row ub, h-col uj)
    const int ub = tid >> 4;          // 0..15 (tid<256)
    const int uj = tid & 15;
    const int bmy = brow0 + ub;       // my batch row
    float c_reg = 0.0f, h_last = 0.0f;
    if (tid < 256) c_reg = c0[bmy * HID + hc0 + uj];

    unsigned int bar_target = 0;
    if (tid == 0) bar_target = *((volatile unsigned int*)&g_bgen[grp * 32]);
    __syncthreads();

    for (int t = 0; t < T_STEPS; t++) {
        // xp prefetch (DRAM latency overlaps staging + MMA)
        float xpi = 0, xpf = 0, xpg = 0, xpo = 0;
        if (tid < 256) {
            const float* xp = g_xproj + ((size_t)t * BATCH + bmy) * GDIM + hc0 + uj;
            xpi = xp[0]; xpf = xp[HID]; xpg = xp[2 * HID]; xpo = xp[3 * HID];
        }
        const float* mrow = mask + t * BATCH;

        // ---- stage group's h[16 x 512] (pre-masked) into A smem ----
        if (t == 0) {
#pragma unroll
            for (int it = 0; it < 4; it++) {
                int idx = tid + it * NTHR;           // 0..2047 float4s
                int row = idx >> 7, f4 = idx & 127;
                int b = brow0 + row;
                float4 v = *(const float4*)(h0 + (size_t)b * HID + f4 * 4);
                float kp = 1.0f - __ldg(&mrow[b]);
                v.x *= kp; v.y *= kp; v.z *= kp; v.w *= kp;
                __nv_bfloat162 h01 = __float22bfloat162_rn(make_float2(v.x, v.y));
                __nv_bfloat162 h23 = __float22bfloat162_rn(make_float2(v.z, v.w));
                float2 f01 = __bfloat1622float2(h01);
                float2 f23 = __bfloat1622float2(h23);
                __nv_bfloat162 l01 = __float22bfloat162_rn(make_float2(v.x - f01.x, v.y - f01.y));
                __nv_bfloat162 l23 = __float22bfloat162_rn(make_float2(v.z - f23.x, v.w - f23.y));
                uint2 hv, lv;
                hv.x = *(uint32_t*)&h01; hv.y = *(uint32_t*)&h23;
                lv.x = *(uint32_t*)&l01; lv.y = *(uint32_t*)&l23;
                *(uint2*)(smraw + OFF_A + swz(row, f4 * 8))        = hv;
                *(uint2*)(smraw + OFF_A + swz(row, 1024 + f4 * 8)) = lv;
            }
        } else {
            const __nv_bfloat16* phi = g_hhi[t & 1] + (size_t)(brow0 + strow) * HID;
            const __nv_bfloat16* plo = g_hlo[t & 1] + (size_t)(brow0 + strow) * HID;
#pragma unroll
            for (int i = 0; i < 4; i++) {
                int u = stj + 32 * i;                   // 0..127; <64 hi, >=64 lo
                uint32_t dst = smb + OFF_A + swz(strow, u << 4);
                const __nv_bfloat16* src = (i < 2) ? (phi + u * 8) : (plo + (u - 64) * 8);
                CP_ASYNC16(dst, src);
            }
            CP_COMMIT();
            CP_WAIT(0);
        }
        __syncthreads();

        // ---- MMA: 3 terms x 16 kc (this warp's k-half), tile m16n8 ----
        float d[4] = {0.f, 0.f, 0.f, 0.f};
#pragma unroll
        for (int term = 0; term < 3; term++) {
            const uint32_t aOff = (term == 1) ? 1024u : 0u;
            const uint32_t bOff = (term == 2) ? 1024u : 0u;
#pragma unroll
            for (int i = 0; i < 16; i++) {
                uint32_t kb = (uint32_t)(kcb + i) << 5;
                uint32_t aaddr = aRowBase + ((aOff + kb + aHi) ^ sA);
                uint32_t baddr = bRowBase + ((bOff + kb + bHi) ^ sB);
                uint32_t a[4], b0, b1;
                LDSM_X4(a[0], a[1], a[2], a[3], aaddr);
                LDSM_X2(b0, b1, baddr);
                MMA16816(d, a, b0, b1);
            }
        }
        {
            // tile rows: lane>>2 and lane>>2+8 (16 rows), cols nt*8+(lane&3)*2
            int gr = lane >> 2;
            int gc = nt * 8 + (lane & 3) * 2;
            float* gp = gates_s + khalf * 1040;   // 16*65
            gp[gr * 65 + gc]           = d[0];
            gp[gr * 65 + gc + 1]       = d[1];
            gp[(gr + 8) * 65 + gc]     = d[2];
            gp[(gr + 8) * 65 + gc + 1] = d[3];
        }
        __syncthreads();

        // ---- LSTM cell update (256 threads, 1 element each) ----
        if (tid < 256) {
            float kp = 1.0f - __ldg(&mrow[bmy]);
            const float* G0 = gates_s + ub * 65;
            const float* G1 = gates_s + 1040 + ub * 65;
            float gi = G0[uj]      + G1[uj]      + xpi;
            float gf = G0[16 + uj] + G1[16 + uj] + xpf;
            float gg = G0[32 + uj] + G1[32 + uj] + xpg;
            float go = G0[48 + uj] + G1[48 + uj] + xpo;
            float cn = sigmoidf_(gf) * (c_reg * kp) + sigmoidf_(gi) * tanhf(gg);
            float hn = sigmoidf_(go) * tanhf(cn);
            c_reg = cn;
            h_last = hn;
            int col = hc0 + uj;
            out[(size_t)t * BATCH * HID + bmy * HID + col] = hn;
            if (t < T_STEPS - 1) {
                float kpn = 1.0f - __ldg(&mask[(t + 1) * BATCH + bmy]);
                float wh = hn * kpn;
                __nv_bfloat16 hh = __float2bfloat16_rn(wh);
                int nb = (t + 1) & 1;
                g_hhi[nb][bmy * HID + col] = hh;
                g_hlo[nb][bmy * HID + col] = __float2bfloat16_rn(wh - __bfloat162float(hh));
            }
        }

        // ---- per-group grid barrier (central counter, tid0 polls) ----
        __syncthreads();
        if (tid == 0) {
            bar_target += 1;
            unsigned int old;
            asm volatile("atom.add.acq_rel.gpu.u32 %0, [%1], 1;"
                         : "=r"(old) : "l"(&g_bcount[grp * 32]) : "memory");
            if (old == GCTA - 1) {
                asm volatile("st.relaxed.gpu.u32 [%0], 0;" :: "l"(&g_bcount[grp * 32]) : "memory");
                asm volatile("red.add.release.gpu.u32 [%0], 1;" :: "l"(&g_bgen[grp * 32]) : "memory");
            } else {
                unsigned int g;
                while (1) {
                    asm volatile("ld.acquire.gpu.u32 %0, [%1];"
                                 : "=r"(g) : "l"(&g_bgen[grp * 32]) : "memory");
                    if ((int)(g - bar_target) >= 0) break;
                    __nanosleep(20);
                }
            }
        }
        __syncthreads();
    }

    // Finals
    if (tid < 256) {
        float* hfin = out + (size_t)T_STEPS * BATCH * HID;
        float* cfin = hfin + BATCH * HID;
        hfin[bmy * HID + hc0 + uj] = h_last;
        cfin[bmy * HID + hc0 + uj] = c_reg;
    }
}

// =====================================================================
extern "C" void kernel_launch(void* const* d_in, const int* in_sizes, int n_in,
                              void* d_out, int out_size) {
    (void)in_sizes; (void)n_in; (void)out_size;
    const float* x    = (const float*)d_in[0];
    const float* h0   = (const float*)d_in[1];
    const float* c0   = (const float*)d_in[2];
    const float* mask = (const float*)d_in[3];
    const float* Wx   = (const float*)d_in[4];
    const float* Wh   = (const float*)d_in[5];
    const float* b    = (const float*)d_in[6];
    float* out = (float*)d_out;

    k_convert_x<<<MROWS * DDIM / 4 / 256, 256>>>(x);
    k_convert_w<<<dim3(GDIM / 32, DDIM / 32), 256>>>(Wx);

    cudaFuncSetAttribute(k_xproj_hmma, cudaFuncAttributeMaxDynamicSharedMemorySize, XSMEM);
    k_xproj_hmma<<<dim3(GDIM / 128, MROWS / 128), 256, XSMEM>>>(b);

    cudaFuncSetAttribute(k_rnn, cudaFuncAttributeMaxDynamicSharedMemorySize, SMEM2);
    k_rnn<<<NCTA, NTHR, SMEM2>>>(h0, c0, mask, Wh, out);
}

// round 12
// speedup vs baseline: 1.2576x; 1.2576x over previous
#include <cuda_runtime.h>
#include <cuda_bf16.h>
#include <math.h>
#include <stdint.h>

// Problem constants (fixed by setup_inputs)
#define T_STEPS 512
#define BATCH   64
#define HID     512
#define GDIM    2048   // 4*H
#define DDIM    512
#define MROWS   (T_STEPS * BATCH)   // 32768

typedef unsigned long long ull;

// ---- scratch (device globals: allocation-free rule) ----
__device__ float g_xproj[(size_t)MROWS * GDIM];                 // 268 MB
__device__ __align__(16) __nv_bfloat16 g_xhi[(size_t)MROWS * DDIM];
__device__ __align__(16) __nv_bfloat16 g_xlo[(size_t)MROWS * DDIM];
__device__ __align__(16) __nv_bfloat16 g_wthi[(size_t)GDIM * DDIM];
__device__ __align__(16) __nv_bfloat16 g_wtlo[(size_t)GDIM * DDIM];
__device__ __align__(16) __nv_bfloat16 g_hhi[2][BATCH * HID];   // double buffer, pre-masked
__device__ __align__(16) __nv_bfloat16 g_hlo[2][BATCH * HID];
// hierarchical barrier: 8 leaf counters 1KB apart, root, gen
__device__ __align__(128) unsigned int g_leaf[8 * 256];
__device__ unsigned int g_root    = 0;
__device__ unsigned int g_bar_gen = 0;

__device__ __forceinline__ float sigmoidf_(float x) { return 1.0f / (1.0f + expf(-x)); }

__device__ __forceinline__ uint32_t smem_u32(const void* p) {
    uint32_t a;
    asm("{ .reg .u64 t; cvta.to.shared.u64 t, %1; cvt.u32.u64 %0, t; }" : "=r"(a) : "l"(p));
    return a;
}

#define CP_ASYNC16(dst, src) \
    asm volatile("cp.async.cg.shared.global [%0], [%1], 16;" :: "r"(dst), "l"(src))
#define CP_COMMIT()   asm volatile("cp.async.commit_group;" ::: "memory")
#define CP_WAIT(n)    asm volatile("cp.async.wait_group %0;" :: "n"(n) : "memory")

#define LDSM_X4(r0, r1, r2, r3, a) \
    asm volatile("ldmatrix.sync.aligned.m8n8.x4.shared.b16 {%0,%1,%2,%3}, [%4];" \
                 : "=r"(r0), "=r"(r1), "=r"(r2), "=r"(r3) : "r"(a))
#define LDSM_X2(r0, r1, a) \
    asm volatile("ldmatrix.sync.aligned.m8n8.x2.shared.b16 {%0,%1}, [%2];" \
                 : "=r"(r0), "=r"(r1) : "r"(a))
#define MMA16816(d, a, b0, b1) \
    asm volatile("mma.sync.aligned.m16n8k16.row.col.f32.bf16.bf16.f32 " \
                 "{%0,%1,%2,%3}, {%4,%5,%6,%7}, {%8,%9}, {%0,%1,%2,%3};" \
                 : "+f"((d)[0]), "+f"((d)[1]), "+f"((d)[2]), "+f"((d)[3]) \
                 : "r"((a)[0]), "r"((a)[1]), "r"((a)[2]), "r"((a)[3]), "r"(b0), "r"(b1))

// =====================================================================
// k_convert_x / k_convert_w (unchanged)
// =====================================================================
__global__ __launch_bounds__(256) void k_convert_x(const float* __restrict__ x) {
    size_t i = (size_t)blockIdx.x * 256 + threadIdx.x;
    float4 v = ((const float4*)x)[i];
    __nv_bfloat162 h01 = __float22bfloat162_rn(make_float2(v.x, v.y));
    __nv_bfloat162 h23 = __float22bfloat162_rn(make_float2(v.z, v.w));
    float2 f01 = __bfloat1622float2(h01);
    float2 f23 = __bfloat1622float2(h23);
    __nv_bfloat162 l01 = __float22bfloat162_rn(make_float2(v.x - f01.x, v.y - f01.y));
    __nv_bfloat162 l23 = __float22bfloat162_rn(make_float2(v.z - f23.x, v.w - f23.y));
    uint2 hv, lv;
    hv.x = *(uint32_t*)&h01; hv.y = *(uint32_t*)&h23;
    lv.x = *(uint32_t*)&l01; lv.y = *(uint32_t*)&l23;
    ((uint2*)g_xhi)[i] = hv;
    ((uint2*)g_xlo)[i] = lv;
}

__global__ __launch_bounds__(256) void k_convert_w(const float* __restrict__ Wx) {
    __shared__ float tile[32][33];
    const int n0 = blockIdx.x * 32;
    const int k0 = blockIdx.y * 32;
    const int c = threadIdx.x & 31, r = threadIdx.x >> 5;
#pragma unroll
    for (int i = 0; i < 4; i++)
        tile[r + i * 8][c] = Wx[(size_t)(k0 + r + i * 8) * GDIM + n0 + c];
    __syncthreads();
#pragma unroll
    for (int i = 0; i < 4; i++) {
        int nn = r + i * 8;
        float v = tile[c][nn];
        __nv_bfloat16 hi = __float2bfloat16_rn(v);
        g_wthi[(size_t)(n0 + nn) * DDIM + k0 + c] = hi;
        g_wtlo[(size_t)(n0 + nn) * DDIM + k0 + c] =
            __float2bfloat16_rn(v - __bfloat162float(hi));
    }
}

// =====================================================================
// k_xproj_hmma (unchanged from round 7)
// =====================================================================
#define XSTAGE 32768
#define XSMEM  (2 * XSTAGE)

__global__ __launch_bounds__(256, 2) void k_xproj_hmma(const float* __restrict__ bias) {
    extern __shared__ char xsm[];
    const uint32_t smb = smem_u32(xsm);
    const int tid = threadIdx.x, lane = tid & 31, wid = tid >> 5;
    const int n0 = blockIdx.x * 128;
    const int m0 = blockIdx.y * 128;
    const int wm = wid & 3, wn = wid >> 2;

    const int sr = tid >> 1;
    const int spl = tid & 1;
    const uint32_t sdst0 = (uint32_t)(sr * 128);
    const int sswz = sr & 7;

    float acc[2][8][4];
#pragma unroll
    for (int mi = 0; mi < 2; mi++)
#pragma unroll
        for (int g = 0; g < 8; g++)
#pragma unroll
            for (int q = 0; q < 4; q++) acc[mi][g][q] = 0.0f;

    const __nv_bfloat16* asrc = (spl ? g_xlo : g_xhi) + (size_t)(m0 + sr) * DDIM;
    const __nv_bfloat16* bsrc = (spl ? g_wtlo : g_wthi) + (size_t)(n0 + sr) * DDIM;

#pragma unroll
    for (int jj = 0; jj < 4; jj++) {
        int j = spl * 4 + jj;
        uint32_t dA = smb + sdst0 + (uint32_t)((j ^ sswz) << 4);
        CP_ASYNC16(dA, asrc + jj * 8);
        CP_ASYNC16(dA + 16384, bsrc + jj * 8);
    }
    CP_COMMIT();

    for (int s = 0; s < 16; s++) {
        if (s < 15) {
            int k0 = (s + 1) * 32;
            uint32_t bufn = ((uint32_t)(s + 1) & 1) * XSTAGE;
#pragma unroll
            for (int jj = 0; jj < 4; jj++) {
                int j = spl * 4 + jj;
                uint32_t dA = smb + bufn + sdst0 + (uint32_t)((j ^ sswz) << 4);
                CP_ASYNC16(dA, asrc + k0 + jj * 8);
                CP_ASYNC16(dA + 16384, bsrc + k0 + jj * 8);
            }
            CP_COMMIT();
            CP_WAIT(1);
        } else {
            CP_WAIT(0);
        }
        __syncthreads();

        const uint32_t Ab = smb + ((uint32_t)s & 1) * XSTAGE;
        const uint32_t Bb = Ab + 16384;
#pragma unroll
        for (int kk = 0; kk < 2; kk++) {
            uint32_t ah[2][4], al[2][4];
#pragma unroll
            for (int mi = 0; mi < 2; mi++) {
                int ar = wm * 32 + mi * 16 + (lane & 15);
                int uh = kk * 2 + ((lane >> 4) & 1);
                uint32_t base = Ab + (uint32_t)(ar * 128);
                int s7 = ar & 7;
                LDSM_X4(ah[mi][0], ah[mi][1], ah[mi][2], ah[mi][3],
                        base + (uint32_t)((uh ^ s7) << 4));
                LDSM_X4(al[mi][0], al[mi][1], al[mi][2], al[mi][3],
                        base + (uint32_t)(((uh + 4) ^ s7) << 4));
            }
#pragma unroll
            for (int g = 0; g < 8; g++) {
                int br = wn * 64 + g * 8 + (lane & 7);
                int ub = kk * 2 + ((lane >> 3) & 1);
                uint32_t base = Bb + (uint32_t)(br * 128);
                int s7 = br & 7;
                uint32_t b0, b1, c0, c1;
                LDSM_X2(b0, b1, base + (uint32_t)((ub ^ s7) << 4));
                LDSM_X2(c0, c1, base + (uint32_t)(((ub + 4) ^ s7) << 4));
#pragma unroll
                for (int mi = 0; mi < 2; mi++) {
                    MMA16816(acc[mi][g], ah[mi], b0, b1);
                    MMA16816(acc[mi][g], al[mi], b0, b1);
                    MMA16816(acc[mi][g], ah[mi], c0, c1);
                }
            }
        }
        __syncthreads();
    }

#pragma unroll
    for (int mi = 0; mi < 2; mi++) {
        int gr = m0 + wm * 32 + mi * 16 + (lane >> 2);
#pragma unroll
        for (int g = 0; g < 8; g++) {
            int gc = n0 + wn * 64 + g * 8 + (lane & 3) * 2;
            float2 bb = *(const float2*)(bias + gc);
            float2 v0 = {acc[mi][g][0] + bb.x, acc[mi][g][1] + bb.y};
            float2 v1 = {acc[mi][g][2] + bb.x, acc[mi][g][3] + bb.y};
            *(float2*)(g_xproj + (size_t)gr * GDIM + gc)       = v0;
            *(float2*)(g_xproj + (size_t)(gr + 8) * GDIM + gc) = v1;
        }
    }
}

// =====================================================================
// k_rnn: persistent masked-LSTM recurrence on HMMA.
// Round 12 = Round 7 EXACT structure (8 MMA warps, 3-term loop,
// tid<256 update) + double-buffered pre-masked h (race fix, pure-copy
// staging) + 2-level hierarchical barrier arrival (8 leaves x 16 + root).
// =====================================================================
#define NCTA 128
#define NTHR 512

#define OFF_A  0        // 64 rows x 2048B = 131072
#define OFF_B  131072   // 16 rows x 2048B = 32768
#define OFF_G  163840   // gates 64 x 17 floats = 4352
#define SMEM2  168448

__device__ __forceinline__ uint32_t swz(int row, int kbyte) {
    return (uint32_t)(row * 2048) + ((((uint32_t)kbyte >> 4) ^ (uint32_t)(row & 7)) << 4)
         + ((uint32_t)kbyte & 15u);
}

__global__ __launch_bounds__(NTHR, 1) void k_rnn(const float* __restrict__ h0,
                                                 const float* __restrict__ c0,
                                                 const float* __restrict__ mask,
                                                 const float* __restrict__ Wh,
                                                 float* __restrict__ out) {
    extern __shared__ char smraw[];
    const uint32_t smb = smem_u32(smraw);
    float* gates_s = (float*)(smraw + OFF_G);
    const int tid = threadIdx.x, lane = tid & 31, wid = tid >> 5;
    const int cta = blockIdx.x, hc0 = cta * 4;
    const int leaf = cta >> 4;   // 8 leaves x 16 CTAs

    // ---- Wh slice -> B smem, split-bf16 (hi kbyte<1024, lo >=1024) ----
#pragma unroll 4
    for (int it = 0; it < 32; it++) {
        int e = tid + it * NTHR;
        int n = e >> 10, k = e & 1023;
        int gcol = (n >> 2) * HID + hc0 + (n & 3);
        float v = Wh[(size_t)(k & 511) * GDIM + gcol];
        __nv_bfloat16 hi = __float2bfloat16_rn(v);
        __nv_bfloat16 bv = (k < 512) ? hi : __float2bfloat16_rn(v - __bfloat162float(hi));
        *(__nv_bfloat16*)(smraw + OFF_B + swz(n, k * 2)) = bv;
    }

    // MMA warp coords (wid < 8): tile (mt, nt)
    const int mt = wid & 3, nt = wid >> 2;
    const int ar = mt * 16 + (lane & 15);
    const uint32_t aRowBase = smb + OFF_A + (uint32_t)ar * 2048;
    const uint32_t sA = (uint32_t)(ar & 7) << 4;
    const uint32_t aHi = (uint32_t)((lane >> 4) & 1) << 4;
    const int br = nt * 8 + (lane & 7);
    const uint32_t bRowBase = smb + OFF_B + (uint32_t)br * 2048;
    const uint32_t sB = (uint32_t)(br & 7) << 4;
    const uint32_t bHi = (uint32_t)((lane >> 3) & 1) << 4;

    // staging coords: one row per 8 threads, 16 x 16B units (8 hi + 8 lo)
    const int strow = tid >> 3;
    const int stj   = tid & 7;
    const uint32_t stdst0 = smb + OFF_A + (uint32_t)(strow * 2048)
                          + ((uint32_t)(stj ^ (strow & 7)) << 4);

    // update mapping (first 256 threads): element (ub, hc0+uj)
    const int ub = tid >> 2;
    const int uj = tid & 3;
    float c_reg = 0.0f, h_last = 0.0f;
    if (tid < 256) c_reg = c0[ub * HID + hc0 + uj];

    unsigned int bar_target = 0;
    if (tid == 0) bar_target = *((volatile unsigned int*)&g_bar_gen);
    __syncthreads();

    for (int t = 0; t < T_STEPS; t++) {
        // xp prefetch (DRAM latency overlaps staging + MMA)
        float xpi = 0, xpf = 0, xpg = 0, xpo = 0;
        if (tid < 256) {
            const float* xp = g_xproj + ((size_t)t * BATCH + ub) * GDIM + hc0 + uj;
            xpi = xp[0]; xpf = xp[HID]; xpg = xp[2 * HID]; xpo = xp[3 * HID];
        }
        const float* mrow = mask + t * BATCH;

        // ---- stage h into A smem (pure copy; mask pre-applied at write) ----
        if (t == 0) {
#pragma unroll
            for (int it = 0; it < 16; it++) {
                int idx = tid + it * NTHR;
                int row = idx >> 7, f4 = idx & 127;
                float4 v = *(const float4*)(h0 + (size_t)row * HID + f4 * 4);
                float kp = 1.0f - __ldg(&mrow[row]);
                v.x *= kp; v.y *= kp; v.z *= kp; v.w *= kp;
                __nv_bfloat162 h01 = __float22bfloat162_rn(make_float2(v.x, v.y));
                __nv_bfloat162 h23 = __float22bfloat162_rn(make_float2(v.z, v.w));
                float2 f01 = __bfloat1622float2(h01);
                float2 f23 = __bfloat1622float2(h23);
                __nv_bfloat162 l01 = __float22bfloat162_rn(make_float2(v.x - f01.x, v.y - f01.y));
                __nv_bfloat162 l23 = __float22bfloat162_rn(make_float2(v.z - f23.x, v.w - f23.y));
                uint2 hv, lv;
                hv.x = *(uint32_t*)&h01; hv.y = *(uint32_t*)&h23;
                lv.x = *(uint32_t*)&l01; lv.y = *(uint32_t*)&l23;
                *(uint2*)(smraw + OFF_A + swz(row, f4 * 8))        = hv;
                *(uint2*)(smraw + OFF_A + swz(row, 1024 + f4 * 8)) = lv;
            }
        } else {
            const __nv_bfloat16* sthi = g_hhi[t & 1] + strow * HID + stj * 8;
            const __nv_bfloat16* stlo = g_hlo[t & 1] + strow * HID + stj * 8;
            uint32_t d = stdst0;
#pragma unroll
            for (int i = 0; i < 8; i++) { CP_ASYNC16(d, sthi + i * 64); d += 128; }
#pragma unroll
            for (int i = 0; i < 8; i++) { CP_ASYNC16(d, stlo + i * 64); d += 128; }
            CP_COMMIT();
            CP_WAIT(0);
        }
        __syncthreads();

        // ---- MMA: 3 terms x 32 k-chunks, one m16n8 tile per warp ----
        if (wid < 8) {
            float d[4] = {0.f, 0.f, 0.f, 0.f};
#pragma unroll
            for (int term = 0; term < 3; term++) {
                const uint32_t aOff = (term == 1) ? 1024u : 0u;
                const uint32_t bOff = (term == 2) ? 1024u : 0u;
#pragma unroll 8
                for (int kc = 0; kc < 32; kc++) {
                    uint32_t kb = (uint32_t)kc << 5;
                    uint32_t aaddr = aRowBase + ((aOff + kb + aHi) ^ sA);
                    uint32_t baddr = bRowBase + ((bOff + kb + bHi) ^ sB);
                    uint32_t a[4], b0, b1;
                    LDSM_X4(a[0], a[1], a[2], a[3], aaddr);
                    LDSM_X2(b0, b1, baddr);
                    MMA16816(d, a, b0, b1);
                }
            }
            int gr = mt * 16 + (lane >> 2);
            int gc = nt * 8 + (lane & 3) * 2;
            gates_s[gr * 17 + gc]           = d[0];
            gates_s[gr * 17 + gc + 1]       = d[1];
            gates_s[(gr + 8) * 17 + gc]     = d[2];
            gates_s[(gr + 8) * 17 + gc + 1] = d[3];
        }
        __syncthreads();

        // ---- LSTM cell update (threads 0..255) ----
        if (tid < 256) {
            float kp = 1.0f - __ldg(&mrow[ub]);
            float gi = gates_s[ub * 17 + 0  + uj] + xpi;
            float gf = gates_s[ub * 17 + 4  + uj] + xpf;
            float gg = gates_s[ub * 17 + 8  + uj] + xpg;
            float go = gates_s[ub * 17 + 12 + uj] + xpo;
            float cprev = c_reg * kp;
            float cn = sigmoidf_(gf) * cprev + sigmoidf_(gi) * tanhf(gg);
            float hn = sigmoidf_(go) * tanhf(cn);
            c_reg = cn;
            h_last = hn;
            int hcol = hc0 + uj;
            out[(size_t)t * BATCH * HID + ub * HID + hcol] = hn;
            if (t < T_STEPS - 1) {
                // pre-apply next step's reset mask at write time
                float kpn = 1.0f - __ldg(&mask[(t + 1) * BATCH + ub]);
                float wh = hn * kpn;
                __nv_bfloat16 hh = __float2bfloat16_rn(wh);
                int nb = (t + 1) & 1;
                g_hhi[nb][ub * HID + hcol] = hh;
                g_hlo[nb][ub * HID + hcol] = __float2bfloat16_rn(wh - __bfloat162float(hh));
            }
        }

        // ---- grid barrier: hierarchical arrive (8 leaves x 16 + root),
        //      wait = R7's proven single-word poll by tid0 only ----
        __syncthreads();
        if (tid == 0) {
            bar_target += 1;
            unsigned int old;
            asm volatile("atom.add.acq_rel.gpu.u32 %0, [%1], 1;"
                         : "=r"(old) : "l"(&g_leaf[leaf * 256]) : "memory");
            if (old == 15) {
                unsigned int rold;
                asm volatile("atom.add.acq_rel.gpu.u32 %0, [%1], 1;"
                             : "=r"(rold) : "l"(&g_root) : "memory");
                if (rold == 7) {
                    // reset leaves + root, then release the generation
#pragma unroll
                    for (int l = 0; l < 8; l++)
                        asm volatile("st.relaxed.gpu.u32 [%0], 0;"
                                     :: "l"(&g_leaf[l * 256]) : "memory");
                    asm volatile("st.relaxed.gpu.u32 [%0], 0;" :: "l"(&g_root) : "memory");
                    asm volatile("red.add.release.gpu.u32 [%0], 1;"
                                 :: "l"(&g_bar_gen) : "memory");
                }
            }
            if (!(tid == 0 && bar_target == 0)) {   // always poll (releaser sees own bump)
                unsigned int g;
                while (1) {
                    asm volatile("ld.acquire.gpu.u32 %0, [%1];"
                                 : "=r"(g) : "l"(&g_bar_gen) : "memory");
                    if ((int)(g - bar_target) >= 0) break;
                    __nanosleep(20);
                }
            }
        }
        __syncthreads();
    }

    // Finals
    if (tid < 256) {
        float* hfin = out + (size_t)T_STEPS * BATCH * HID;
        float* cfin = hfin + BATCH * HID;
        hfin[ub * HID + hc0 + uj] = h_last;
        cfin[ub * HID + hc0 + uj] = c_reg;
    }
}

// =====================================================================
extern "C" void kernel_launch(void* const* d_in, const int* in_sizes, int n_in,
                              void* d_out, int out_size) {
    (void)in_sizes; (void)n_in; (void)out_size;
    const float* x    = (const float*)d_in[0];
    const float* h0   = (const float*)d_in[1];
    const float* c0   = (const float*)d_in[2];
    const float* mask = (const float*)d_in[3];
    const float* Wx   = (const float*)d_in[4];
    const float* Wh   = (const float*)d_in[5];
    const float* b    = (const float*)d_in[6];
    float* out = (float*)d_out;

    k_convert_x<<<MROWS * DDIM / 4 / 256, 256>>>(x);
    k_convert_w<<<dim3(GDIM / 32, DDIM / 32), 256>>>(Wx);

    cudaFuncSetAttribute(k_xproj_hmma, cudaFuncAttributeMaxDynamicSharedMemorySize, XSMEM);
    k_xproj_hmma<<<dim3(GDIM / 128, MROWS / 128), 256, XSMEM>>>(b);

    cudaFuncSetAttribute(k_rnn, cudaFuncAttributeMaxDynamicSharedMemorySize, SMEM2);
    k_rnn<<<NCTA, NTHR, SMEM2>>>(h0, c0, mask, Wh, out);
}

// round 13
// speedup vs baseline: 1.4008x; 1.1138x over previous
#include <cuda_runtime.h>
#include <cuda_bf16.h>
#include <math.h>
#include <stdint.h>

// Problem constants (fixed by setup_inputs)
#define T_STEPS 512
#define BATCH   64
#define HID     512
#define GDIM    2048   // 4*H
#define DDIM    512
#define MROWS   (T_STEPS * BATCH)   // 32768

typedef unsigned long long ull;

// ---- scratch (device globals: allocation-free rule) ----
__device__ float g_xproj[(size_t)MROWS * GDIM];                 // 268 MB
__device__ __align__(16) __nv_bfloat16 g_xhi[(size_t)MROWS * DDIM];
__device__ __align__(16) __nv_bfloat16 g_xlo[(size_t)MROWS * DDIM];
__device__ __align__(16) __nv_bfloat16 g_wthi[(size_t)GDIM * DDIM];
__device__ __align__(16) __nv_bfloat16 g_wtlo[(size_t)GDIM * DDIM];
__device__ __align__(16) __nv_bfloat16 g_hhi[BATCH * HID];
__device__ __align__(16) __nv_bfloat16 g_hlo[BATCH * HID];
__device__ unsigned int g_bar_count = 0;
__device__ unsigned int g_bar_gen   = 0;

__device__ __forceinline__ float sigmoidf_(float x) { return 1.0f / (1.0f + expf(-x)); }

__device__ __forceinline__ uint32_t smem_u32(const void* p) {
    uint32_t a;
    asm("{ .reg .u64 t; cvta.to.shared.u64 t, %1; cvt.u32.u64 %0, t; }" : "=r"(a) : "l"(p));
    return a;
}

#define CP_ASYNC16(dst, src) \
    asm volatile("cp.async.cg.shared.global [%0], [%1], 16;" :: "r"(dst), "l"(src))
#define CP_COMMIT()   asm volatile("cp.async.commit_group;" ::: "memory")
#define CP_WAIT(n)    asm volatile("cp.async.wait_group %0;" :: "n"(n) : "memory")

#define LDSM_X4(r0, r1, r2, r3, a) \
    asm volatile("ldmatrix.sync.aligned.m8n8.x4.shared.b16 {%0,%1,%2,%3}, [%4];" \
                 : "=r"(r0), "=r"(r1), "=r"(r2), "=r"(r3) : "r"(a))
#define LDSM_X2(r0, r1, a) \
    asm volatile("ldmatrix.sync.aligned.m8n8.x2.shared.b16 {%0,%1}, [%2];" \
                 : "=r"(r0), "=r"(r1) : "r"(a))
#define MMA16816(d, a, b0, b1) \
    asm volatile("mma.sync.aligned.m16n8k16.row.col.f32.bf16.bf16.f32 " \
                 "{%0,%1,%2,%3}, {%4,%5,%6,%7}, {%8,%9}, {%0,%1,%2,%3};" \
                 : "+f"((d)[0]), "+f"((d)[1]), "+f"((d)[2]), "+f"((d)[3]) \
                 : "r"((a)[0]), "r"((a)[1]), "r"((a)[2]), "r"((a)[3]), "r"(b0), "r"(b1))

// =====================================================================
// k_convert_x / k_convert_w (unchanged)
// =====================================================================
__global__ __launch_bounds__(256) void k_convert_x(const float* __restrict__ x) {
    size_t i = (size_t)blockIdx.x * 256 + threadIdx.x;
    float4 v = ((const float4*)x)[i];
    __nv_bfloat162 h01 = __float22bfloat162_rn(make_float2(v.x, v.y));
    __nv_bfloat162 h23 = __float22bfloat162_rn(make_float2(v.z, v.w));
    float2 f01 = __bfloat1622float2(h01);
    float2 f23 = __bfloat1622float2(h23);
    __nv_bfloat162 l01 = __float22bfloat162_rn(make_float2(v.x - f01.x, v.y - f01.y));
    __nv_bfloat162 l23 = __float22bfloat162_rn(make_float2(v.z - f23.x, v.w - f23.y));
    uint2 hv, lv;
    hv.x = *(uint32_t*)&h01; hv.y = *(uint32_t*)&h23;
    lv.x = *(uint32_t*)&l01; lv.y = *(uint32_t*)&l23;
    ((uint2*)g_xhi)[i] = hv;
    ((uint2*)g_xlo)[i] = lv;
}

__global__ __launch_bounds__(256) void k_convert_w(const float* __restrict__ Wx) {
    __shared__ float tile[32][33];
    const int n0 = blockIdx.x * 32;
    const int k0 = blockIdx.y * 32;
    const int c = threadIdx.x & 31, r = threadIdx.x >> 5;
#pragma unroll
    for (int i = 0; i < 4; i++)
        tile[r + i * 8][c] = Wx[(size_t)(k0 + r + i * 8) * GDIM + n0 + c];
    __syncthreads();
#pragma unroll
    for (int i = 0; i < 4; i++) {
        int nn = r + i * 8;
        float v = tile[c][nn];
        __nv_bfloat16 hi = __float2bfloat16_rn(v);
        g_wthi[(size_t)(n0 + nn) * DDIM + k0 + c] = hi;
        g_wtlo[(size_t)(n0 + nn) * DDIM + k0 + c] =
            __float2bfloat16_rn(v - __bfloat162float(hi));
    }
}

// =====================================================================
// k_xproj_hmma: 3-stage cp.async pipeline, ONE __syncthreads per stage.
// Buffer reuse safety: issue into (s+2)%3 happens after the top-of-loop
// sync of iteration s, which guarantees all warps completed compute(s-1)
// (the previous reader of that buffer).
// =====================================================================
#define XSTAGE 32768   // A 16KB + B 16KB per stage
#define XNST   3
#define XSMEM  (XNST * XSTAGE)

__global__ __launch_bounds__(256, 2) void k_xproj_hmma(const float* __restrict__ bias) {
    extern __shared__ char xsm[];
    const uint32_t smb = smem_u32(xsm);
    const int tid = threadIdx.x, lane = tid & 31, wid = tid >> 5;
    const int n0 = blockIdx.x * 128;
    const int m0 = blockIdx.y * 128;
    const int wm = wid & 3, wn = wid >> 2;

    const int sr = tid >> 1;
    const int spl = tid & 1;
    const uint32_t sdst0 = (uint32_t)(sr * 128);
    const int sswz = sr & 7;

    float acc[2][8][4];
#pragma unroll
    for (int mi = 0; mi < 2; mi++)
#pragma unroll
        for (int g = 0; g < 8; g++)
#pragma unroll
            for (int q = 0; q < 4; q++) acc[mi][g][q] = 0.0f;

    const __nv_bfloat16* asrc = (spl ? g_xlo : g_xhi) + (size_t)(m0 + sr) * DDIM;
    const __nv_bfloat16* bsrc = (spl ? g_wtlo : g_wthi) + (size_t)(n0 + sr) * DDIM;

    // prologue: stages 0 and 1
#pragma unroll
    for (int ps = 0; ps < 2; ps++) {
        uint32_t buf = smb + (uint32_t)ps * XSTAGE;
#pragma unroll
        for (int jj = 0; jj < 4; jj++) {
            int j = spl * 4 + jj;
            uint32_t dA = buf + sdst0 + (uint32_t)((j ^ sswz) << 4);
            CP_ASYNC16(dA, asrc + ps * 32 + jj * 8);
            CP_ASYNC16(dA + 16384, bsrc + ps * 32 + jj * 8);
        }
        CP_COMMIT();
    }

    for (int s = 0; s < 16; s++) {
        if (s < 15) { CP_WAIT(1); } else { CP_WAIT(0); }
        __syncthreads();

        // issue stage s+2 (buffer free: compute(s-1) finished by all warps
        // before the sync above)
        if (s < 14) {
            int k0 = (s + 2) * 32;
            uint32_t buf = smb + (uint32_t)((s + 2) % XNST) * XSTAGE;
#pragma unroll
            for (int jj = 0; jj < 4; jj++) {
                int j = spl * 4 + jj;
                uint32_t dA = buf + sdst0 + (uint32_t)((j ^ sswz) << 4);
                CP_ASYNC16(dA, asrc + k0 + jj * 8);
                CP_ASYNC16(dA + 16384, bsrc + k0 + jj * 8);
            }
            CP_COMMIT();
        }

        const uint32_t Ab = smb + (uint32_t)(s % XNST) * XSTAGE;
        const uint32_t Bb = Ab + 16384;
#pragma unroll
        for (int kk = 0; kk < 2; kk++) {
            uint32_t ah[2][4], al[2][4];
#pragma unroll
            for (int mi = 0; mi < 2; mi++) {
                int ar = wm * 32 + mi * 16 + (lane & 15);
                int uh = kk * 2 + ((lane >> 4) & 1);
                uint32_t base = Ab + (uint32_t)(ar * 128);
                int s7 = ar & 7;
                LDSM_X4(ah[mi][0], ah[mi][1], ah[mi][2], ah[mi][3],
                        base + (uint32_t)((uh ^ s7) << 4));
                LDSM_X4(al[mi][0], al[mi][1], al[mi][2], al[mi][3],
                        base + (uint32_t)(((uh + 4) ^ s7) << 4));
            }
#pragma unroll
            for (int g = 0; g < 8; g++) {
                int br = wn * 64 + g * 8 + (lane & 7);
                int ub = kk * 2 + ((lane >> 3) & 1);
                uint32_t base = Bb + (uint32_t)(br * 128);
                int s7 = br & 7;
                uint32_t b0, b1, c0, c1;
                LDSM_X2(b0, b1, base + (uint32_t)((ub ^ s7) << 4));
                LDSM_X2(c0, c1, base + (uint32_t)(((ub + 4) ^ s7) << 4));
#pragma unroll
                for (int mi = 0; mi < 2; mi++) {
                    MMA16816(acc[mi][g], ah[mi], b0, b1);
                    MMA16816(acc[mi][g], al[mi], b0, b1);
                    MMA16816(acc[mi][g], ah[mi], c0, c1);
                }
            }
        }
    }

#pragma unroll
    for (int mi = 0; mi < 2; mi++) {
        int gr = m0 + wm * 32 + mi * 16 + (lane >> 2);
#pragma unroll
        for (int g = 0; g < 8; g++) {
            int gc = n0 + wn * 64 + g * 8 + (lane & 3) * 2;
            float2 bb = *(const float2*)(bias + gc);
            float2 v0 = {acc[mi][g][0] + bb.x, acc[mi][g][1] + bb.y};
            float2 v1 = {acc[mi][g][2] + bb.x, acc[mi][g][3] + bb.y};
            *(float2*)(g_xproj + (size_t)gr * GDIM + gc)       = v0;
            *(float2*)(g_xproj + (size_t)(gr + 8) * GDIM + gc) = v1;
        }
    }
}

// =====================================================================
// k_rnn: BYTE-EXACT round-7 kernel (measured 3.18 ms).
// =====================================================================
#define NCTA 128
#define NTHR 512

#define OFF_A  0        // 64 rows x 2048B = 131072
#define OFF_B  131072   // 16 rows x 2048B = 32768
#define OFF_G  163840   // gates 64 x 17 floats = 4352
#define SMEM2  168448

__device__ __forceinline__ uint32_t swz(int row, int kbyte) {
    return (uint32_t)(row * 2048) + ((((uint32_t)kbyte >> 4) ^ (uint32_t)(row & 7)) << 4)
         + ((uint32_t)kbyte & 15u);
}

__global__ __launch_bounds__(NTHR, 1) void k_rnn(const float* __restrict__ h0,
                                                 const float* __restrict__ c0,
                                                 const float* __restrict__ mask,
                                                 const float* __restrict__ Wh,
                                                 float* __restrict__ out) {
    extern __shared__ char smraw[];
    const uint32_t smb = smem_u32(smraw);
    float* gates_s = (float*)(smraw + OFF_G);
    const int tid = threadIdx.x, lane = tid & 31, wid = tid >> 5;
    const int cta = blockIdx.x, hc0 = cta * 4;

    // ---- Wh slice -> B smem, split-bf16 (hi at kbyte<1024, lo >=1024) ----
#pragma unroll 4
    for (int it = 0; it < 32; it++) {
        int e = tid + it * NTHR;
        int n = e >> 10, k = e & 1023;
        int gcol = (n >> 2) * HID + hc0 + (n & 3);
        float v = Wh[(size_t)(k & 511) * GDIM + gcol];
        __nv_bfloat16 hi = __float2bfloat16_rn(v);
        __nv_bfloat16 bv = (k < 512) ? hi : __float2bfloat16_rn(v - __bfloat162float(hi));
        *(__nv_bfloat16*)(smraw + OFF_B + swz(n, k * 2)) = bv;
    }

    // MMA warp coords (wid < 8)
    const int mt = wid & 3, nt = wid >> 2;
    const int ar = mt * 16 + (lane & 15);
    const uint32_t aRowBase = smb + OFF_A + (uint32_t)ar * 2048;
    const uint32_t sA = (uint32_t)(ar & 7) << 4;
    const uint32_t aHi = (uint32_t)((lane >> 4) & 1) << 4;
    const int br = nt * 8 + (lane & 7);
    const uint32_t bRowBase = smb + OFF_B + (uint32_t)br * 2048;
    const uint32_t sB = (uint32_t)(br & 7) << 4;
    const uint32_t bHi = (uint32_t)((lane >> 3) & 1) << 4;

    // staging coords: one row per 8 threads, 16 x 16B units each (linear)
    const int strow = tid >> 3;
    const int stj   = tid & 7;
    const uint32_t stdst0 = smb + OFF_A + (uint32_t)(strow * 2048)
                          + ((uint32_t)(stj ^ (strow & 7)) << 4);
    const __nv_bfloat16* sthi = g_hhi + strow * HID + stj * 8;
    const __nv_bfloat16* stlo = g_hlo + strow * HID + stj * 8;

    // update mapping (first 256 threads)
    const int ub = tid >> 2;
    const int uj = tid & 3;
    float c_reg = 0.0f, h_last = 0.0f;
    if (tid < 256) c_reg = c0[ub * HID + hc0 + uj];

    unsigned int bar_target = 0;
    if (tid == 0) bar_target = *((volatile unsigned int*)&g_bar_gen);
    __syncthreads();

    for (int t = 0; t < T_STEPS; t++) {
        // xp prefetch (DRAM latency overlaps staging)
        float xpi = 0, xpf = 0, xpg = 0, xpo = 0;
        if (tid < 256) {
            const float* xp = g_xproj + ((size_t)t * BATCH + ub) * GDIM + hc0 + uj;
            xpi = xp[0]; xpf = xp[HID]; xpg = xp[2 * HID]; xpo = xp[3 * HID];
        }
        const float* mrow = mask + t * BATCH;

        // ---- stage h into A smem ----
        if (t == 0) {
#pragma unroll
            for (int it = 0; it < 16; it++) {
                int idx = tid + it * NTHR;
                int row = idx >> 7, f4 = idx & 127;
                float4 v = *(const float4*)(h0 + (size_t)row * HID + f4 * 4);
                float kp = 1.0f - __ldg(&mrow[row]);
                v.x *= kp; v.y *= kp; v.z *= kp; v.w *= kp;
                __nv_bfloat162 h01 = __float22bfloat162_rn(make_float2(v.x, v.y));
                __nv_bfloat162 h23 = __float22bfloat162_rn(make_float2(v.z, v.w));
                float2 f01 = __bfloat1622float2(h01);
                float2 f23 = __bfloat1622float2(h23);
                __nv_bfloat162 l01 = __float22bfloat162_rn(make_float2(v.x - f01.x, v.y - f01.y));
                __nv_bfloat162 l23 = __float22bfloat162_rn(make_float2(v.z - f23.x, v.w - f23.y));
                uint2 hv, lv;
                hv.x = *(uint32_t*)&h01; hv.y = *(uint32_t*)&h23;
                lv.x = *(uint32_t*)&l01; lv.y = *(uint32_t*)&l23;
                *(uint2*)(smraw + OFF_A + swz(row, f4 * 8))        = hv;
                *(uint2*)(smraw + OFF_A + swz(row, 1024 + f4 * 8)) = lv;
            }
        } else {
            float mval = __ldg(&mrow[strow]);
            uint32_t d = stdst0;
#pragma unroll
            for (int i = 0; i < 8; i++) { CP_ASYNC16(d, sthi + i * 64); d += 128; }
#pragma unroll
            for (int i = 0; i < 8; i++) { CP_ASYNC16(d, stlo + i * 64); d += 128; }
            CP_COMMIT();
            CP_WAIT(0);
            if (mval != 0.0f) {
                uint4 z = {0u, 0u, 0u, 0u};
                uint32_t dz = stdst0;
#pragma unroll
                for (int i = 0; i < 16; i++) {
                    asm volatile("st.shared.v4.b32 [%0], {%1,%2,%3,%4};"
                                 :: "r"(dz), "r"(z.x), "r"(z.y), "r"(z.z), "r"(z.w));
                    dz += 128;
                }
            }
        }
        __syncthreads();

        // ---- MMA: 3 terms x 32 k-chunks, one m16n8 tile per warp ----
        if (wid < 8) {
            float d[4] = {0.f, 0.f, 0.f, 0.f};
#pragma unroll
            for (int term = 0; term < 3; term++) {
                const uint32_t aOff = (term == 1) ? 1024u : 0u;
                const uint32_t bOff = (term == 2) ? 1024u : 0u;
#pragma unroll 8
                for (int kc = 0; kc < 32; kc++) {
                    uint32_t kb = (uint32_t)kc << 5;
                    uint32_t aaddr = aRowBase + ((aOff + kb + aHi) ^ sA);
                    uint32_t baddr = bRowBase + ((bOff + kb + bHi) ^ sB);
                    uint32_t a[4], b0, b1;
                    LDSM_X4(a[0], a[1], a[2], a[3], aaddr);
                    LDSM_X2(b0, b1, baddr);
                    MMA16816(d, a, b0, b1);
                }
            }
            int gr = mt * 16 + (lane >> 2);
            int gc = nt * 8 + (lane & 3) * 2;
            gates_s[gr * 17 + gc]           = d[0];
            gates_s[gr * 17 + gc + 1]       = d[1];
            gates_s[(gr + 8) * 17 + gc]     = d[2];
            gates_s[(gr + 8) * 17 + gc + 1] = d[3];
        }
        __syncthreads();

        // ---- LSTM cell update (threads 0..255) ----
        if (tid < 256) {
            float kp = 1.0f - __ldg(&mrow[ub]);
            float gi = gates_s[ub * 17 + 0  + uj] + xpi;
            float gf = gates_s[ub * 17 + 4  + uj] + xpf;
            float gg = gates_s[ub * 17 + 8  + uj] + xpg;
            float go = gates_s[ub * 17 + 12 + uj] + xpo;
            float cprev = c_reg * kp;
            float cn = sigmoidf_(gf) * cprev + sigmoidf_(gi) * tanhf(gg);
            float hn = sigmoidf_(go) * tanhf(cn);
            c_reg = cn;
            h_last = hn;
            int hcol = hc0 + uj;
            out[(size_t)t * BATCH * HID + ub * HID + hcol] = hn;
            __nv_bfloat16 hh = __float2bfloat16_rn(hn);
            g_hhi[ub * HID + hcol] = hh;
            g_hlo[ub * HID + hcol] = __float2bfloat16_rn(hn - __bfloat162float(hh));
        }

        // ---- grid barrier: central counter, tid0-only polling ----
        __syncthreads();
        if (tid == 0) {
            bar_target += 1;
            unsigned int old;
            asm volatile("atom.add.acq_rel.gpu.u32 %0, [%1], 1;"
                         : "=r"(old) : "l"(&g_bar_count) : "memory");
            if (old == NCTA - 1) {
                asm volatile("st.relaxed.gpu.u32 [%0], 0;" :: "l"(&g_bar_count) : "memory");
                asm volatile("red.add.release.gpu.u32 [%0], 1;" :: "l"(&g_bar_gen) : "memory");
            } else {
                unsigned int g;
                while (1) {
                    asm volatile("ld.acquire.gpu.u32 %0, [%1];"
                                 : "=r"(g) : "l"(&g_bar_gen) : "memory");
                    if ((int)(g - bar_target) >= 0) break;
                    __nanosleep(20);
                }
            }
        }
        __syncthreads();
    }

    // Finals
    if (tid < 256) {
        float* hfin = out + (size_t)T_STEPS * BATCH * HID;
        float* cfin = hfin + BATCH * HID;
        hfin[ub * HID + hc0 + uj] = h_last;
        cfin[ub * HID + hc0 + uj] = c_reg;
    }
}

// =====================================================================
extern "C" void kernel_launch(void* const* d_in, const int* in_sizes, int n_in,
                              void* d_out, int out_size) {
    (void)in_sizes; (void)n_in; (void)out_size;
    const float* x    = (const float*)d_in[0];
    const float* h0   = (const float*)d_in[1];
    const float* c0   = (const float*)d_in[2];
    const float* mask = (const float*)d_in[3];
    const float* Wx   = (const float*)d_in[4];
    const float* Wh   = (const float*)d_in[5];
    const float* b    = (const float*)d_in[6];
    float* out = (float*)d_out;

    k_convert_x<<<MROWS * DDIM / 4 / 256, 256>>>(x);
    k_convert_w<<<dim3(GDIM / 32, DDIM / 32), 256>>>(Wx);

    cudaFuncSetAttribute(k_xproj_hmma, cudaFuncAttributeMaxDynamicSharedMemorySize, XSMEM);
    k_xproj_hmma<<<dim3(GDIM / 128, MROWS / 128), 256, XSMEM>>>(b);

    cudaFuncSetAttribute(k_rnn, cudaFuncAttributeMaxDynamicSharedMemorySize, SMEM2);
    k_rnn<<<NCTA, NTHR, SMEM2>>>(h0, c0, mask, Wh, out);
}

// round 14
// speedup vs baseline: 1.4440x; 1.0309x over previous
#include <cuda_runtime.h>
#include <cuda_bf16.h>
#include <math.h>
#include <stdint.h>

// Problem constants (fixed by setup_inputs)
#define T_STEPS 512
#define BATCH   64
#define HID     512
#define GDIM    2048   // 4*H
#define DDIM    512
#define MROWS   (T_STEPS * BATCH)   // 32768

typedef unsigned long long ull;

// ---- scratch (device globals: allocation-free rule) ----
__device__ float g_xproj[(size_t)MROWS * GDIM];                 // 268 MB
__device__ __align__(16) __nv_bfloat16 g_xhi[(size_t)MROWS * DDIM];
__device__ __align__(16) __nv_bfloat16 g_xlo[(size_t)MROWS * DDIM];
__device__ __align__(16) __nv_bfloat16 g_wthi[(size_t)GDIM * DDIM];
__device__ __align__(16) __nv_bfloat16 g_wtlo[(size_t)GDIM * DDIM];
__device__ __align__(16) __nv_bfloat16 g_hhi[BATCH * HID];
__device__ __align__(16) __nv_bfloat16 g_hlo[BATCH * HID];
__device__ unsigned int g_bar_count = 0;
__device__ unsigned int g_bar_gen   = 0;

// fast activations: MUFU-based, rel err ~1e-6 (NOT tanh.approx ~5e-4)
__device__ __forceinline__ float fsig(float x) {
    return __fdividef(1.0f, 1.0f + __expf(-x));
}
__device__ __forceinline__ float ftanh_(float x) {
    float t = __expf(-2.0f * fabsf(x));
    float r = __fdividef(1.0f - t, 1.0f + t);
    return copysignf(r, x);
}

__device__ __forceinline__ uint32_t smem_u32(const void* p) {
    uint32_t a;
    asm("{ .reg .u64 t; cvta.to.shared.u64 t, %1; cvt.u32.u64 %0, t; }" : "=r"(a) : "l"(p));
    return a;
}

#define CP_ASYNC16(dst, src) \
    asm volatile("cp.async.cg.shared.global [%0], [%1], 16;" :: "r"(dst), "l"(src))
#define CP_COMMIT()   asm volatile("cp.async.commit_group;" ::: "memory")
#define CP_WAIT(n)    asm volatile("cp.async.wait_group %0;" :: "n"(n) : "memory")

#define LDSM_X4(r0, r1, r2, r3, a) \
    asm volatile("ldmatrix.sync.aligned.m8n8.x4.shared.b16 {%0,%1,%2,%3}, [%4];" \
                 : "=r"(r0), "=r"(r1), "=r"(r2), "=r"(r3) : "r"(a))
#define LDSM_X2(r0, r1, a) \
    asm volatile("ldmatrix.sync.aligned.m8n8.x2.shared.b16 {%0,%1}, [%2];" \
                 : "=r"(r0), "=r"(r1) : "r"(a))
#define MMA16816(d, a, b0, b1) \
    asm volatile("mma.sync.aligned.m16n8k16.row.col.f32.bf16.bf16.f32 " \
                 "{%0,%1,%2,%3}, {%4,%5,%6,%7}, {%8,%9}, {%0,%1,%2,%3};" \
                 : "+f"((d)[0]), "+f"((d)[1]), "+f"((d)[2]), "+f"((d)[3]) \
                 : "r"((a)[0]), "r"((a)[1]), "r"((a)[2]), "r"((a)[3]), "r"(b0), "r"(b1))

// =====================================================================
// k_convert_x / k_convert_w (unchanged)
// =====================================================================
__global__ __launch_bounds__(256) void k_convert_x(const float* __restrict__ x) {
    size_t i = (size_t)blockIdx.x * 256 + threadIdx.x;
    float4 v = ((const float4*)x)[i];
    __nv_bfloat162 h01 = __float22bfloat162_rn(make_float2(v.x, v.y));
    __nv_bfloat162 h23 = __float22bfloat162_rn(make_float2(v.z, v.w));
    float2 f01 = __bfloat1622float2(h01);
    float2 f23 = __bfloat1622float2(h23);
    __nv_bfloat162 l01 = __float22bfloat162_rn(make_float2(v.x - f01.x, v.y - f01.y));
    __nv_bfloat162 l23 = __float22bfloat162_rn(make_float2(v.z - f23.x, v.w - f23.y));
    uint2 hv, lv;
    hv.x = *(uint32_t*)&h01; hv.y = *(uint32_t*)&h23;
    lv.x = *(uint32_t*)&l01; lv.y = *(uint32_t*)&l23;
    ((uint2*)g_xhi)[i] = hv;
    ((uint2*)g_xlo)[i] = lv;
}

__global__ __launch_bounds__(256) void k_convert_w(const float* __restrict__ Wx) {
    __shared__ float tile[32][33];
    const int n0 = blockIdx.x * 32;
    const int k0 = blockIdx.y * 32;
    const int c = threadIdx.x & 31, r = threadIdx.x >> 5;
#pragma unroll
    for (int i = 0; i < 4; i++)
        tile[r + i * 8][c] = Wx[(size_t)(k0 + r + i * 8) * GDIM + n0 + c];
    __syncthreads();
#pragma unroll
    for (int i = 0; i < 4; i++) {
        int nn = r + i * 8;
        float v = tile[c][nn];
        __nv_bfloat16 hi = __float2bfloat16_rn(v);
        g_wthi[(size_t)(n0 + nn) * DDIM + k0 + c] = hi;
        g_wtlo[(size_t)(n0 + nn) * DDIM + k0 + c] =
            __float2bfloat16_rn(v - __bfloat162float(hi));
    }
}

// =====================================================================
// k_xproj_hmma: 3-stage cp.async pipeline (unchanged from round 13)
// =====================================================================
#define XSTAGE 32768
#define XNST   3
#define XSMEM  (XNST * XSTAGE)

__global__ __launch_bounds__(256, 2) void k_xproj_hmma(const float* __restrict__ bias) {
    extern __shared__ char xsm[];
    const uint32_t smb = smem_u32(xsm);
    const int tid = threadIdx.x, lane = tid & 31, wid = tid >> 5;
    const int n0 = blockIdx.x * 128;
    const int m0 = blockIdx.y * 128;
    const int wm = wid & 3, wn = wid >> 2;

    const int sr = tid >> 1;
    const int spl = tid & 1;
    const uint32_t sdst0 = (uint32_t)(sr * 128);
    const int sswz = sr & 7;

    float acc[2][8][4];
#pragma unroll
    for (int mi = 0; mi < 2; mi++)
#pragma unroll
        for (int g = 0; g < 8; g++)
#pragma unroll
            for (int q = 0; q < 4; q++) acc[mi][g][q] = 0.0f;

    const __nv_bfloat16* asrc = (spl ? g_xlo : g_xhi) + (size_t)(m0 + sr) * DDIM;
    const __nv_bfloat16* bsrc = (spl ? g_wtlo : g_wthi) + (size_t)(n0 + sr) * DDIM;

#pragma unroll
    for (int ps = 0; ps < 2; ps++) {
        uint32_t buf = smb + (uint32_t)ps * XSTAGE;
#pragma unroll
        for (int jj = 0; jj < 4; jj++) {
            int j = spl * 4 + jj;
            uint32_t dA = buf + sdst0 + (uint32_t)((j ^ sswz) << 4);
            CP_ASYNC16(dA, asrc + ps * 32 + jj * 8);
            CP_ASYNC16(dA + 16384, bsrc + ps * 32 + jj * 8);
        }
        CP_COMMIT();
    }

    for (int s = 0; s < 16; s++) {
        if (s < 15) { CP_WAIT(1); } else { CP_WAIT(0); }
        __syncthreads();

        if (s < 14) {
            int k0 = (s + 2) * 32;
            uint32_t buf = smb + (uint32_t)((s + 2) % XNST) * XSTAGE;
#pragma unroll
            for (int jj = 0; jj < 4; jj++) {
                int j = spl * 4 + jj;
                uint32_t dA = buf + sdst0 + (uint32_t)((j ^ sswz) << 4);
                CP_ASYNC16(dA, asrc + k0 + jj * 8);
                CP_ASYNC16(dA + 16384, bsrc + k0 + jj * 8);
            }
            CP_COMMIT();
        }

        const uint32_t Ab = smb + (uint32_t)(s % XNST) * XSTAGE;
        const uint32_t Bb = Ab + 16384;
#pragma unroll
        for (int kk = 0; kk < 2; kk++) {
            uint32_t ah[2][4], al[2][4];
#pragma unroll
            for (int mi = 0; mi < 2; mi++) {
                int ar = wm * 32 + mi * 16 + (lane & 15);
                int uh = kk * 2 + ((lane >> 4) & 1);
                uint32_t base = Ab + (uint32_t)(ar * 128);
                int s7 = ar & 7;
                LDSM_X4(ah[mi][0], ah[mi][1], ah[mi][2], ah[mi][3],
                        base + (uint32_t)((uh ^ s7) << 4));
                LDSM_X4(al[mi][0], al[mi][1], al[mi][2], al[mi][3],
                        base + (uint32_t)(((uh + 4) ^ s7) << 4));
            }
#pragma unroll
            for (int g = 0; g < 8; g++) {
                int br = wn * 64 + g * 8 + (lane & 7);
                int ub = kk * 2 + ((lane >> 3) & 1);
                uint32_t base = Bb + (uint32_t)(br * 128);
                int s7 = br & 7;
                uint32_t b0, b1, c0, c1;
                LDSM_X2(b0, b1, base + (uint32_t)((ub ^ s7) << 4));
                LDSM_X2(c0, c1, base + (uint32_t)(((ub + 4) ^ s7) << 4));
#pragma unroll
                for (int mi = 0; mi < 2; mi++) {
                    MMA16816(acc[mi][g], ah[mi], b0, b1);
                    MMA16816(acc[mi][g], al[mi], b0, b1);
                    MMA16816(acc[mi][g], ah[mi], c0, c1);
                }
            }
        }
    }

#pragma unroll
    for (int mi = 0; mi < 2; mi++) {
        int gr = m0 + wm * 32 + mi * 16 + (lane >> 2);
#pragma unroll
        for (int g = 0; g < 8; g++) {
            int gc = n0 + wn * 64 + g * 8 + (lane & 3) * 2;
            float2 bb = *(const float2*)(bias + gc);
            float2 v0 = {acc[mi][g][0] + bb.x, acc[mi][g][1] + bb.y};
            float2 v1 = {acc[mi][g][2] + bb.x, acc[mi][g][3] + bb.y};
            *(float2*)(g_xproj + (size_t)gr * GDIM + gc)       = v0;
            *(float2*)(g_xproj + (size_t)(gr + 8) * GDIM + gc) = v1;
        }
    }
}

// =====================================================================
// k_rnn: round-7 structure; round-14 deltas ONLY in:
//   (a) MMA inner loop: dual accumulators (halved HMMA RAW chain) and
//       B ldmatrix.x4 over kc pairs (halved B LDSM count)
//   (b) update phase: MUFU-based fast sigmoid/tanh
// =====================================================================
#define NCTA 128
#define NTHR 512

#define OFF_A  0        // 64 rows x 2048B = 131072
#define OFF_B  131072   // 16 rows x 2048B = 32768
#define OFF_G  163840   // gates 64 x 17 floats = 4352
#define SMEM2  168448

__device__ __forceinline__ uint32_t swz(int row, int kbyte) {
    return (uint32_t)(row * 2048) + ((((uint32_t)kbyte >> 4) ^ (uint32_t)(row & 7)) << 4)
         + ((uint32_t)kbyte & 15u);
}

__global__ __launch_bounds__(NTHR, 1) void k_rnn(const float* __restrict__ h0,
                                                 const float* __restrict__ c0,
                                                 const float* __restrict__ mask,
                                                 const float* __restrict__ Wh,
                                                 float* __restrict__ out) {
    extern __shared__ char smraw[];
    const uint32_t smb = smem_u32(smraw);
    float* gates_s = (float*)(smraw + OFF_G);
    const int tid = threadIdx.x, lane = tid & 31, wid = tid >> 5;
    const int cta = blockIdx.x, hc0 = cta * 4;

    // ---- Wh slice -> B smem, split-bf16 (hi at kbyte<1024, lo >=1024) ----
#pragma unroll 4
    for (int it = 0; it < 32; it++) {
        int e = tid + it * NTHR;
        int n = e >> 10, k = e & 1023;
        int gcol = (n >> 2) * HID + hc0 + (n & 3);
        float v = Wh[(size_t)(k & 511) * GDIM + gcol];
        __nv_bfloat16 hi = __float2bfloat16_rn(v);
        __nv_bfloat16 bv = (k < 512) ? hi : __float2bfloat16_rn(v - __bfloat162float(hi));
        *(__nv_bfloat16*)(smraw + OFF_B + swz(n, k * 2)) = bv;
    }

    // MMA warp coords (wid < 8)
    const int mt = wid & 3, nt = wid >> 2;
    const int ar = mt * 16 + (lane & 15);
    const uint32_t aRowBase = smb + OFF_A + (uint32_t)ar * 2048;
    const uint32_t sA = (uint32_t)(ar & 7) << 4;
    const uint32_t aHi = (uint32_t)((lane >> 4) & 1) << 4;
    const int br = nt * 8 + (lane & 7);
    const uint32_t bRowBase = smb + OFF_B + (uint32_t)br * 2048;
    const uint32_t sB = (uint32_t)(br & 7) << 4;
    const uint32_t bQ = (uint32_t)((lane >> 3) & 3) << 4;   // x4: 4 groups of 16B

    // staging coords: one row per 8 threads, 16 x 16B units each (linear)
    const int strow = tid >> 3;
    const int stj   = tid & 7;
    const uint32_t stdst0 = smb + OFF_A + (uint32_t)(strow * 2048)
                          + ((uint32_t)(stj ^ (strow & 7)) << 4);
    const __nv_bfloat16* sthi = g_hhi + strow * HID + stj * 8;
    const __nv_bfloat16* stlo = g_hlo + strow * HID + stj * 8;

    // update mapping (first 256 threads)
    const int ub = tid >> 2;
    const int uj = tid & 3;
    float c_reg = 0.0f, h_last = 0.0f;
    if (tid < 256) c_reg = c0[ub * HID + hc0 + uj];

    unsigned int bar_target = 0;
    if (tid == 0) bar_target = *((volatile unsigned int*)&g_bar_gen);
    __syncthreads();

    for (int t = 0; t < T_STEPS; t++) {
        // xp prefetch (DRAM latency overlaps staging)
        float xpi = 0, xpf = 0, xpg = 0, xpo = 0;
        if (tid < 256) {
            const float* xp = g_xproj + ((size_t)t * BATCH + ub) * GDIM + hc0 + uj;
            xpi = xp[0]; xpf = xp[HID]; xpg = xp[2 * HID]; xpo = xp[3 * HID];
        }
        const float* mrow = mask + t * BATCH;

        // ---- stage h into A smem ----
        if (t == 0) {
#pragma unroll
            for (int it = 0; it < 16; it++) {
                int idx = tid + it * NTHR;
                int row = idx >> 7, f4 = idx & 127;
                float4 v = *(const float4*)(h0 + (size_t)row * HID + f4 * 4);
                float kp = 1.0f - __ldg(&mrow[row]);
                v.x *= kp; v.y *= kp; v.z *= kp; v.w *= kp;
                __nv_bfloat162 h01 = __float22bfloat162_rn(make_float2(v.x, v.y));
                __nv_bfloat162 h23 = __float22bfloat162_rn(make_float2(v.z, v.w));
                float2 f01 = __bfloat1622float2(h01);
                float2 f23 = __bfloat1622float2(h23);
                __nv_bfloat162 l01 = __float22bfloat162_rn(make_float2(v.x - f01.x, v.y - f01.y));
                __nv_bfloat162 l23 = __float22bfloat162_rn(make_float2(v.z - f23.x, v.w - f23.y));
                uint2 hv, lv;
                hv.x = *(uint32_t*)&h01; hv.y = *(uint32_t*)&h23;
                lv.x = *(uint32_t*)&l01; lv.y = *(uint32_t*)&l23;
                *(uint2*)(smraw + OFF_A + swz(row, f4 * 8))        = hv;
                *(uint2*)(smraw + OFF_A + swz(row, 1024 + f4 * 8)) = lv;
            }
        } else {
            float mval = __ldg(&mrow[strow]);
            uint32_t d = stdst0;
#pragma unroll
            for (int i = 0; i < 8; i++) { CP_ASYNC16(d, sthi + i * 64); d += 128; }
#pragma unroll
            for (int i = 0; i < 8; i++) { CP_ASYNC16(d, stlo + i * 64); d += 128; }
            CP_COMMIT();
            CP_WAIT(0);
            if (mval != 0.0f) {
                uint4 z = {0u, 0u, 0u, 0u};
                uint32_t dz = stdst0;
#pragma unroll
                for (int i = 0; i < 16; i++) {
                    asm volatile("st.shared.v4.b32 [%0], {%1,%2,%3,%4};"
                                 :: "r"(dz), "r"(z.x), "r"(z.y), "r"(z.z), "r"(z.w));
                    dz += 128;
                }
            }
        }
        __syncthreads();

        // ---- MMA: 3 terms x 32 kc; kc paired, dual accumulators ----
        if (wid < 8) {
            float d0[4] = {0.f, 0.f, 0.f, 0.f};
            float d1[4] = {0.f, 0.f, 0.f, 0.f};
#pragma unroll
            for (int term = 0; term < 3; term++) {
                const uint32_t aOff = (term == 1) ? 1024u : 0u;
                const uint32_t bOff = (term == 2) ? 1024u : 0u;
#pragma unroll 4
                for (int kc = 0; kc < 32; kc += 2) {
                    uint32_t kb = (uint32_t)kc << 5;
                    uint32_t a0r[4], a1r[4], b0, b1, b2, b3;
                    LDSM_X4(a0r[0], a0r[1], a0r[2], a0r[3],
                            aRowBase + ((aOff + kb + aHi) ^ sA));
                    LDSM_X4(a1r[0], a1r[1], a1r[2], a1r[3],
                            aRowBase + ((aOff + kb + 32u + aHi) ^ sA));
                    LDSM_X4(b0, b1, b2, b3,
                            bRowBase + ((bOff + kb + bQ) ^ sB));
                    MMA16816(d0, a0r, b0, b1);
                    MMA16816(d1, a1r, b2, b3);
                }
            }
#pragma unroll
            for (int q = 0; q < 4; q++) d0[q] += d1[q];
            int gr = mt * 16 + (lane >> 2);
            int gc = nt * 8 + (lane & 3) * 2;
            gates_s[gr * 17 + gc]           = d0[0];
            gates_s[gr * 17 + gc + 1]       = d0[1];
            gates_s[(gr + 8) * 17 + gc]     = d0[2];
            gates_s[(gr + 8) * 17 + gc + 1] = d0[3];
        }
        __syncthreads();

        // ---- LSTM cell update (threads 0..255, fast activations) ----
        if (tid < 256) {
            float kp = 1.0f - __ldg(&mrow[ub]);
            float gi = gates_s[ub * 17 + 0  + uj] + xpi;
            float gf = gates_s[ub * 17 + 4  + uj] + xpf;
            float gg = gates_s[ub * 17 + 8  + uj] + xpg;
            float go = gates_s[ub * 17 + 12 + uj] + xpo;
            float cprev = c_reg * kp;
            float cn = fsig(gf) * cprev + fsig(gi) * ftanh_(gg);
            float hn = fsig(go) * ftanh_(cn);
            c_reg = cn;
            h_last = hn;
            int hcol = hc0 + uj;
            out[(size_t)t * BATCH * HID + ub * HID + hcol] = hn;
            __nv_bfloat16 hh = __float2bfloat16_rn(hn);
            g_hhi[ub * HID + hcol] = hh;
            g_hlo[ub * HID + hcol] = __float2bfloat16_rn(hn - __bfloat162float(hh));
        }

        // ---- grid barrier: central counter, tid0-only polling ----
        __syncthreads();
        if (tid == 0) {
            bar_target += 1;
            unsigned int old;
            asm volatile("atom.add.acq_rel.gpu.u32 %0, [%1], 1;"
                         : "=r"(old) : "l"(&g_bar_count) : "memory");
            if (old == NCTA - 1) {
                asm volatile("st.relaxed.gpu.u32 [%0], 0;" :: "l"(&g_bar_count) : "memory");
                asm volatile("red.add.release.gpu.u32 [%0], 1;" :: "l"(&g_bar_gen) : "memory");
            } else {
                unsigned int g;
                while (1) {
                    asm volatile("ld.acquire.gpu.u32 %0, [%1];"
                                 : "=r"(g) : "l"(&g_bar_gen) : "memory");
                    if ((int)(g - bar_target) >= 0) break;
                    __nanosleep(20);
                }
            }
        }
        __syncthreads();
    }

    // Finals
    if (tid < 256) {
        float* hfin = out + (size_t)T_STEPS * BATCH * HID;
        float* cfin = hfin + BATCH * HID;
        hfin[ub * HID + hc0 + uj] = h_last;
        cfin[ub * HID + hc0 + uj] = c_reg;
    }
}

// =====================================================================
extern "C" void kernel_launch(void* const* d_in, const int* in_sizes, int n_in,
                              void* d_out, int out_size) {
    (void)in_sizes; (void)n_in; (void)out_size;
    const float* x    = (const float*)d_in[0];
    const float* h0   = (const float*)d_in[1];
    const float* c0   = (const float*)d_in[2];
    const float* mask = (const float*)d_in[3];
    const float* Wx   = (const float*)d_in[4];
    const float* Wh   = (const float*)d_in[5];
    const float* b    = (const float*)d_in[6];
    float* out = (float*)d_out;

    k_convert_x<<<MROWS * DDIM / 4 / 256, 256>>>(x);
    k_convert_w<<<dim3(GDIM / 32, DDIM / 32), 256>>>(Wx);

    cudaFuncSetAttribute(k_xproj_hmma, cudaFuncAttributeMaxDynamicSharedMemorySize, XSMEM);
    k_xproj_hmma<<<dim3(GDIM / 128, MROWS / 128), 256, XSMEM>>>(b);

    cudaFuncSetAttribute(k_rnn, cudaFuncAttributeMaxDynamicSharedMemorySize, SMEM2);
    k_rnn<<<NCTA, NTHR, SMEM2>>>(h0, c0, mask, Wh, out);
}